// round 7
// baseline (speedup 1.0000x reference)
#include <cuda_runtime.h>
#include <cstdint>
#include <cstdio>

#define LSEQ 4096
#define HID  512
#define TH3  1536      // 3*HID
#define GB   32        // blocks per GRU direction
#define SLICE 16       // HID / GB
#define NROW 48        // 3*SLICE rows of w_hh per block
#define KF1  9216      // 1024 * 9 augmented K for KAN layer 1
#define KF2  4608      // 512 * 9  augmented K for KAN layer 2

// ---------------- scratch (device globals; no allocation allowed) ----------
__device__ float g_gi[2][LSEQ * TH3];        // input gates, fwd/bwd
__device__ float g_dirout[2][LSEQ * HID];    // GRU outputs per direction
__device__ float g_A1[LSEQ * KF1];           // augmented features KAN1
__device__ float g_W1[HID * KF1];            // augmented weights  KAN1
__device__ float g_A2[LSEQ * KF2];
__device__ float g_W2[HID * KF2];
__device__ float g_a2[LSEQ * HID];           // sigmoid output of KAN2
__device__ float g_h[2][2][HID];             // [dir][parity][i] hidden double buffer
__device__ int   g_flag[2][GB];              // per-block completed-step flags (1 line/dir)
__device__ float g_yp[32][HID];              // partial sums for final reduction

// ---------------- init: reset recurrence state each replay -----------------
__global__ void k_init() {
    int i = blockIdx.x * blockDim.x + threadIdx.x;
    if (i < 2 * 2 * HID) ((float*)g_h)[i] = 0.f;
    if (i < 2 * GB) ((int*)g_flag)[i] = -1;
}

// ---------------- TF32 tensor-core GEMM (unchanged from R6) ----------------
#define GPAD 36

__device__ __forceinline__ uint32_t to_tf32(float x) {
    uint32_t r;
    asm("cvt.rna.tf32.f32 %0, %1;" : "=r"(r) : "f"(x));   // tf32 dest is .b32
    return r;
}
__device__ __forceinline__ float to_tf32f(float x) {
    return __uint_as_float(to_tf32(x));
}

__device__ __forceinline__ void mma_tf32(float* c, const uint32_t* a, const uint32_t* b) {
    asm volatile(
        "mma.sync.aligned.m16n8k8.row.col.f32.tf32.tf32.f32 "
        "{%0,%1,%2,%3}, {%4,%5,%6,%7}, {%8,%9}, {%0,%1,%2,%3};"
        : "+f"(c[0]), "+f"(c[1]), "+f"(c[2]), "+f"(c[3])
        : "r"(a[0]), "r"(a[1]), "r"(a[2]), "r"(a[3]), "r"(b[0]), "r"(b[1]));
}

template <int ACT>
__global__ void __launch_bounds__(256, 1) k_gemm(
    const float* __restrict__ A, const float* __restrict__ B,
    const float* __restrict__ bias, float* __restrict__ C,
    int M, int N, int K)
{
    __shared__ float As[128 * GPAD];
    __shared__ float Bs[128 * GPAD];
    int tid = threadIdx.x, lane = tid & 31, warp = tid >> 5;
    int wm = warp >> 2, wn = warp & 3;          // warp grid 2 (M) x 4 (N)
    int gid = lane >> 2, tig = lane & 3;
    int bm = blockIdx.y, bn = blockIdx.x;
    const float* Ab = A + (size_t)bm * 128 * K;
    const float* Bb = B + (size_t)bn * 128 * K;

    int r = tid >> 1, seg = (tid & 1) * 16;     // staging: row r, 16 cols

    float4 sa[4], sb[4];
    float acc[4][4][4];
#pragma unroll
    for (int mt = 0; mt < 4; mt++)
#pragma unroll
        for (int nt = 0; nt < 4; nt++)
#pragma unroll
            for (int q = 0; q < 4; q++) acc[mt][nt][q] = 0.f;

    // prefetch slab 0
#pragma unroll
    for (int i = 0; i < 4; i++) {
        sa[i] = *(const float4*)(Ab + (size_t)r * K + seg + 4 * i);
        sb[i] = *(const float4*)(Bb + (size_t)r * K + seg + 4 * i);
    }

    for (int k0 = 0; k0 < K; k0 += 32) {
        // stage regs -> smem (tf32-rounded)
#pragma unroll
        for (int i = 0; i < 4; i++) {
            float4 a = sa[i], b = sb[i];
            a.x = to_tf32f(a.x); a.y = to_tf32f(a.y);
            a.z = to_tf32f(a.z); a.w = to_tf32f(a.w);
            b.x = to_tf32f(b.x); b.y = to_tf32f(b.y);
            b.z = to_tf32f(b.z); b.w = to_tf32f(b.w);
            *(float4*)&As[r * GPAD + seg + 4 * i] = a;
            *(float4*)&Bs[r * GPAD + seg + 4 * i] = b;
        }
        __syncthreads();

        // prefetch next slab
        if (k0 + 32 < K) {
#pragma unroll
            for (int i = 0; i < 4; i++) {
                sa[i] = *(const float4*)(Ab + (size_t)r * K + k0 + 32 + seg + 4 * i);
                sb[i] = *(const float4*)(Bb + (size_t)r * K + k0 + 32 + seg + 4 * i);
            }
        }

#pragma unroll
        for (int ks = 0; ks < 4; ks++) {
            int kk = ks * 8;
            uint32_t bf[4][2];
#pragma unroll
            for (int nt = 0; nt < 4; nt++) {
                int n = wn * 32 + nt * 8 + gid;
                bf[nt][0] = __float_as_uint(Bs[n * GPAD + kk + tig]);
                bf[nt][1] = __float_as_uint(Bs[n * GPAD + kk + tig + 4]);
            }
#pragma unroll
            for (int mt = 0; mt < 4; mt++) {
                int m = wm * 64 + mt * 16;
                uint32_t af[4];
                af[0] = __float_as_uint(As[(m + gid) * GPAD + kk + tig]);
                af[1] = __float_as_uint(As[(m + gid + 8) * GPAD + kk + tig]);
                af[2] = __float_as_uint(As[(m + gid) * GPAD + kk + tig + 4]);
                af[3] = __float_as_uint(As[(m + gid + 8) * GPAD + kk + tig + 4]);
#pragma unroll
                for (int nt = 0; nt < 4; nt++)
                    mma_tf32(acc[mt][nt], af, bf[nt]);
            }
        }
        __syncthreads();
    }

    // epilogue
#pragma unroll
    for (int mt = 0; mt < 4; mt++) {
#pragma unroll
        for (int nt = 0; nt < 4; nt++) {
            int row0 = bm * 128 + wm * 64 + mt * 16 + gid;
            int col  = bn * 128 + wn * 32 + nt * 8 + 2 * tig;
            float v[4];
#pragma unroll
            for (int q = 0; q < 4; q++) v[q] = acc[mt][nt][q];
            if (bias) {
                float b0 = bias[col], b1 = bias[col + 1];
                v[0] += b0; v[1] += b1; v[2] += b0; v[3] += b1;
            }
            if (ACT == 1) {
#pragma unroll
                for (int q = 0; q < 4; q++) v[q] = v[q] > 0.f ? v[q] : 0.f;
            } else if (ACT == 2) {
#pragma unroll
                for (int q = 0; q < 4; q++) v[q] = 1.f / (1.f + expf(-v[q]));
            }
            *(float2*)&C[(size_t)row0 * N + col]       = make_float2(v[0], v[1]);
            *(float2*)&C[(size_t)(row0 + 8) * N + col] = make_float2(v[2], v[3]);
        }
    }
}

// ---------------- GRU recurrence: low-latency release/acquire handoff ------
// grid (GB, 2). Per step:
//   warp0 acquire-polls the 32-flag line; one syncthreads releases all warps;
//   every warp loads full h_prev straight into registers (ldcg, L2);
//   dot partials -> double-buffered smem; one syncthreads;
//   warp0 lanes<16 compute gates (h_prev of own slice kept in a register),
//   store h + out, syncwarp, lane0 release-stores the flag.
// No __threadfence, no nanosleep, no smem h staging.
__device__ __forceinline__ int ld_acquire(const int* p) {
    int v;
    asm volatile("ld.acquire.gpu.b32 %0, [%1];" : "=r"(v) : "l"(p) : "memory");
    return v;
}
__device__ __forceinline__ void st_release(int* p, int v) {
    asm volatile("st.release.gpu.b32 [%0], %1;" :: "l"(p), "r"(v) : "memory");
}

__global__ void __launch_bounds__(256, 1) k_gru(
    const float* __restrict__ whhf, const float* __restrict__ whhb,
    const float* __restrict__ bhhf, const float* __restrict__ bhhb)
{
    int dir = blockIdx.y;
    int b   = blockIdx.x;
    const float* gi  = g_gi[dir];
    float*       out = g_dirout[dir];
    const float* whh = dir ? whhb : whhf;
    const float* bhh = dir ? bhhb : bhhf;
    int i0 = b * SLICE;
    int tid = threadIdx.x, lane = tid & 31, warp = tid >> 5;
    int* flags = g_flag[dir];

    __shared__ float dot_s[2][NROW];

    // weights: thread (warp, lane) owns rows q = warp*6 + r, cols lane + 32*m
    float w[6][16];
#pragma unroll
    for (int r = 0; r < 6; r++) {
        int q = warp * 6 + r;
        int grow = (q / SLICE) * HID + i0 + (q % SLICE);
#pragma unroll
        for (int m = 0; m < 16; m++)
            w[r][m] = whh[(size_t)grow * HID + lane + 32 * m];
    }

    // gate-thread private state (tid < 16 only)
    float hprev = 0.f, bhr = 0.f, bhz = 0.f, bhn = 0.f;
    if (tid < SLICE) {
        bhr = bhh[0 * HID + i0 + tid];
        bhz = bhh[1 * HID + i0 + tid];
        bhn = bhh[2 * HID + i0 + tid];
    }
    __syncthreads();

    for (int t = 0; t < LSEQ; t++) {
        int tt = dir ? (LSEQ - 1 - t) : t;

        // gate threads prefetch gi for this step (latency hidden by spin)
        float gir = 0.f, giz = 0.f, gin = 0.f;
        if (tid < SLICE) {
            const float* g = gi + (size_t)tt * TH3 + i0 + tid;
            gir = __ldg(g);
            giz = __ldg(g + HID);
            gin = __ldg(g + 2 * HID);
        }

        // warp0 acquire-polls all 32 flags; barrier propagates the ordering
        if (t > 0) {
            if (warp == 0) {
                int f;
                do {
                    f = ld_acquire(&flags[lane]);
                } while (!__all_sync(0xffffffffu, f >= t - 1));
            }
            __syncthreads();
        }

        // full h_prev straight into registers (L2; producer lines not in L1)
        const float* hg = g_h[dir][t & 1];
        float hv[16];
#pragma unroll
        for (int m = 0; m < 16; m++) hv[m] = __ldcg(&hg[lane + 32 * m]);

        float acc[6];
#pragma unroll
        for (int r = 0; r < 6; r++) {
            float a = 0.f;
#pragma unroll
            for (int m = 0; m < 16; m++) a = fmaf(w[r][m], hv[m], a);
            acc[r] = a;
        }
#pragma unroll
        for (int r = 0; r < 6; r++) {
#pragma unroll
            for (int off = 16; off > 0; off >>= 1)
                acc[r] += __shfl_down_sync(0xffffffffu, acc[r], off);
        }
        if (lane == 0) {
#pragma unroll
            for (int r = 0; r < 6; r++) dot_s[t & 1][warp * 6 + r] = acc[r];
        }
        __syncthreads();

        if (warp == 0) {
            if (tid < SLICE) {
                int j = tid, i = i0 + j;
                float hr = dot_s[t & 1][j]             + bhr;
                float hz = dot_s[t & 1][SLICE + j]     + bhz;
                float hn = dot_s[t & 1][2 * SLICE + j] + bhn;
                float rg = 1.f / (1.f + expf(-(gir + hr)));
                float zg = 1.f / (1.f + expf(-(giz + hz)));
                float ng = tanhf(gin + rg * hn);
                float hnew = (1.f - zg) * ng + zg * hprev;
                hprev = hnew;
                g_h[dir][(t + 1) & 1][i] = hnew;
                out[(size_t)tt * HID + i] = hnew;
            }
            __syncwarp();
            if (lane == 0) st_release(&flags[b], t);   // release: h visible first
        }
    }
}

// ---------------- KAN feature expansion ------------------------------------
__device__ __forceinline__ void kan_feats(float x, float* f) {
    f[0] = x / (1.f + expf(-x));   // silu
    float b[11];
#pragma unroll
    for (int j = 0; j < 11; j++) {
        float gj  = 0.4f * (float)(j - 3) - 1.0f;
        float gj1 = 0.4f * (float)(j - 2) - 1.0f;
        b[j] = (x >= gj && x < gj1) ? 1.f : 0.f;
    }
#pragma unroll
    for (int k = 1; k <= 3; k++) {
#pragma unroll
        for (int j = 0; j < 11; j++) {
            if (j + k < 11) {
                float gj   = 0.4f * (float)(j - 3)     - 1.f;
                float gjk  = 0.4f * (float)(j + k - 3) - 1.f;
                float gj1  = 0.4f * (float)(j - 2)     - 1.f;
                float gjk1 = 0.4f * (float)(j + k - 2) - 1.f;
                b[j] = (x - gj) / (gjk - gj) * b[j]
                     + (gjk1 - x) / (gjk1 - gj1) * b[j + 1];
            }
        }
    }
#pragma unroll
    for (int q = 0; q < 8; q++) f[1 + q] = b[q];
}

__global__ void k_expand1(float* __restrict__ A) {
    int idx = blockIdx.x * 256 + threadIdx.x;   // n*1024 + i
    int n = idx >> 10, i = idx & 1023;
    float x = (i < HID) ? g_dirout[0][n * HID + i]
                        : g_dirout[1][n * HID + (i - HID)];
    float f[9]; kan_feats(x, f);
    float* dst = A + (size_t)n * KF1 + i * 9;
#pragma unroll
    for (int c = 0; c < 9; c++) dst[c] = f[c];
}

__global__ void k_expand2(const float* __restrict__ a1, float* __restrict__ A) {
    int idx = blockIdx.x * 256 + threadIdx.x;   // n*512 + i
    float x = a1[idx];
    int n = idx >> 9, i = idx & 511;
    float f[9]; kan_feats(x, f);
    float* dst = A + (size_t)n * KF2 + i * 9;
#pragma unroll
    for (int c = 0; c < 9; c++) dst[c] = f[c];
}

__global__ void k_buildW(const float* __restrict__ bw, const float* __restrict__ sw,
                         const float* __restrict__ sc, float* __restrict__ W, int INF) {
    int idx = blockIdx.x * 256 + threadIdx.x;
    if (idx >= HID * INF) return;
    int i = idx % INF;
    int o = idx / INF;
    float s = sc[idx];
    float* dst = W + (size_t)o * INF * 9 + i * 9;
    dst[0] = bw[idx];
#pragma unroll
    for (int q = 0; q < 8; q++) dst[1 + q] = sw[(size_t)idx * 8 + q] * s;
}

// ---------------- final reduction y = a2^T p -------------------------------
__global__ void k_ypart(const float* __restrict__ p) {
    int bb = blockIdx.x;
    int o  = threadIdx.x;
    float acc = 0.f;
    int n0 = bb * 128;
#pragma unroll 4
    for (int n = n0; n < n0 + 128; n++)
        acc = fmaf(g_a2[(size_t)n * HID + o], p[n], acc);
    g_yp[bb][o] = acc;
}

__global__ void k_yfinal(float* __restrict__ y) {
    int o = blockIdx.x * 256 + threadIdx.x;
    float acc = 0.f;
#pragma unroll
    for (int c = 0; c < 32; c++) acc += g_yp[c][o];
    y[o] = acc;
}

// ---------------- launch ---------------------------------------------------
extern "C" void kernel_launch(void* const* d_in, const int* in_sizes, int n_in,
                              void* d_out, int out_size) {
    const float* h    = (const float*)d_in[0];
    const float* p    = (const float*)d_in[1];
    const float* wihf = (const float*)d_in[2];
    const float* whhf = (const float*)d_in[3];
    const float* bihf = (const float*)d_in[4];
    const float* bhhf = (const float*)d_in[5];
    const float* wihb = (const float*)d_in[6];
    const float* whhb = (const float*)d_in[7];
    const float* bihb = (const float*)d_in[8];
    const float* bhhb = (const float*)d_in[9];
    const float* bw1  = (const float*)d_in[10];
    const float* sw1  = (const float*)d_in[11];
    const float* sc1  = (const float*)d_in[12];
    const float* bw2  = (const float*)d_in[13];
    const float* sw2  = (const float*)d_in[14];
    const float* sc2  = (const float*)d_in[15];
    float* out = (float*)d_out;     // [0:512) = y, [512:) = a_1 (L,HID)

    float *gi_base, *A1, *W1, *A2, *W2, *a2;
    cudaGetSymbolAddress((void**)&gi_base, g_gi);
    cudaGetSymbolAddress((void**)&A1, g_A1);
    cudaGetSymbolAddress((void**)&W1, g_W1);
    cudaGetSymbolAddress((void**)&A2, g_A2);
    cudaGetSymbolAddress((void**)&W2, g_W2);
    cudaGetSymbolAddress((void**)&a2, g_a2);
    float* gi_f = gi_base;
    float* gi_b = gi_base + (size_t)LSEQ * TH3;

    k_init<<<8, 256>>>();

    // input-gate GEMMs: gi = h @ w_ih^T + b_ih
    dim3 ggi(TH3 / 128, LSEQ / 128);
    k_gemm<0><<<ggi, 256>>>(h, wihf, bihf, gi_f, LSEQ, TH3, HID);
    k_gemm<0><<<ggi, 256>>>(h, wihb, bihb, gi_b, LSEQ, TH3, HID);

    // weight expansion for both KAN layers (independent of GRU output)
    k_buildW<<<(HID * 1024 + 255) / 256, 256>>>(bw1, sw1, sc1, W1, 1024);
    k_buildW<<<(HID * HID + 255) / 256, 256>>>(bw2, sw2, sc2, W2, HID);

    // recurrence, both directions concurrently
    k_gru<<<dim3(GB, 2), 256>>>(whhf, whhb, bhhf, bhhb);

    // KAN layer 1
    k_expand1<<<(LSEQ * 1024) / 256, 256>>>(A1);
    k_gemm<1><<<dim3(HID / 128, LSEQ / 128), 256>>>(A1, W1, nullptr, out + HID, LSEQ, HID, KF1);

    // KAN layer 2
    k_expand2<<<(LSEQ * HID) / 256, 256>>>(out + HID, A2);
    k_gemm<2><<<dim3(HID / 128, LSEQ / 128), 256>>>(A2, W2, nullptr, a2, LSEQ, HID, KF2);

    // y = a2^T p (deterministic two-stage reduction)
    k_ypart<<<32, 512>>>(p);
    k_yfinal<<<2, 256>>>(out);
}

// round 8
// speedup vs baseline: 1.1840x; 1.1840x over previous
#include <cuda_runtime.h>
#include <cstdint>
#include <cstdio>

#define LSEQ 4096
#define HID  512
#define TH3  1536      // 3*HID
#define GB   32        // blocks per GRU direction
#define SLICE 16       // HID / GB
#define NROW 48        // 3*SLICE rows of w_hh per block
#define KF1  9216      // 1024 * 9 augmented K for KAN layer 1
#define KF2  4608      // 512 * 9  augmented K for KAN layer 2

// ---------------- scratch (device globals; no allocation allowed) ----------
__device__ float g_gi[2][LSEQ * TH3];        // input gates, fwd/bwd
__device__ float g_dirout[2][LSEQ * HID];    // GRU outputs per direction
__device__ float g_A1[LSEQ * KF1];           // augmented features KAN1
__device__ float g_W1[HID * KF1];            // augmented weights  KAN1
__device__ float g_A2[LSEQ * KF2];
__device__ float g_W2[HID * KF2];
__device__ float g_a2[LSEQ * HID];           // sigmoid output of KAN2
__device__ float g_h[2][2][HID];             // [dir][parity][i] hidden double buffer
__device__ int   g_flag[2][GB];              // per-block completed-step flags (1 line/dir)
__device__ float g_yp[32][HID];              // partial sums for final reduction

// ---------------- init: reset recurrence state each replay -----------------
__global__ void k_init() {
    int i = blockIdx.x * blockDim.x + threadIdx.x;
    if (i < 2 * 2 * HID) ((float*)g_h)[i] = 0.f;
    if (i < 2 * GB) ((int*)g_flag)[i] = -1;
}

// ---------------- TF32 tensor-core GEMM (unchanged, proven) ----------------
#define GPAD 36

__device__ __forceinline__ uint32_t to_tf32(float x) {
    uint32_t r;
    asm("cvt.rna.tf32.f32 %0, %1;" : "=r"(r) : "f"(x));   // tf32 dest is .b32
    return r;
}
__device__ __forceinline__ float to_tf32f(float x) {
    return __uint_as_float(to_tf32(x));
}

__device__ __forceinline__ void mma_tf32(float* c, const uint32_t* a, const uint32_t* b) {
    asm volatile(
        "mma.sync.aligned.m16n8k8.row.col.f32.tf32.tf32.f32 "
        "{%0,%1,%2,%3}, {%4,%5,%6,%7}, {%8,%9}, {%0,%1,%2,%3};"
        : "+f"(c[0]), "+f"(c[1]), "+f"(c[2]), "+f"(c[3])
        : "r"(a[0]), "r"(a[1]), "r"(a[2]), "r"(a[3]), "r"(b[0]), "r"(b[1]));
}

template <int ACT>
__global__ void __launch_bounds__(256, 1) k_gemm(
    const float* __restrict__ A, const float* __restrict__ B,
    const float* __restrict__ bias, float* __restrict__ C,
    int M, int N, int K)
{
    __shared__ float As[128 * GPAD];
    __shared__ float Bs[128 * GPAD];
    int tid = threadIdx.x, lane = tid & 31, warp = tid >> 5;
    int wm = warp >> 2, wn = warp & 3;          // warp grid 2 (M) x 4 (N)
    int gid = lane >> 2, tig = lane & 3;
    int bm = blockIdx.y, bn = blockIdx.x;
    const float* Ab = A + (size_t)bm * 128 * K;
    const float* Bb = B + (size_t)bn * 128 * K;

    int r = tid >> 1, seg = (tid & 1) * 16;     // staging: row r, 16 cols

    float4 sa[4], sb[4];
    float acc[4][4][4];
#pragma unroll
    for (int mt = 0; mt < 4; mt++)
#pragma unroll
        for (int nt = 0; nt < 4; nt++)
#pragma unroll
            for (int q = 0; q < 4; q++) acc[mt][nt][q] = 0.f;

    // prefetch slab 0
#pragma unroll
    for (int i = 0; i < 4; i++) {
        sa[i] = *(const float4*)(Ab + (size_t)r * K + seg + 4 * i);
        sb[i] = *(const float4*)(Bb + (size_t)r * K + seg + 4 * i);
    }

    for (int k0 = 0; k0 < K; k0 += 32) {
        // stage regs -> smem (tf32-rounded)
#pragma unroll
        for (int i = 0; i < 4; i++) {
            float4 a = sa[i], b = sb[i];
            a.x = to_tf32f(a.x); a.y = to_tf32f(a.y);
            a.z = to_tf32f(a.z); a.w = to_tf32f(a.w);
            b.x = to_tf32f(b.x); b.y = to_tf32f(b.y);
            b.z = to_tf32f(b.z); b.w = to_tf32f(b.w);
            *(float4*)&As[r * GPAD + seg + 4 * i] = a;
            *(float4*)&Bs[r * GPAD + seg + 4 * i] = b;
        }
        __syncthreads();

        // prefetch next slab
        if (k0 + 32 < K) {
#pragma unroll
            for (int i = 0; i < 4; i++) {
                sa[i] = *(const float4*)(Ab + (size_t)r * K + k0 + 32 + seg + 4 * i);
                sb[i] = *(const float4*)(Bb + (size_t)r * K + k0 + 32 + seg + 4 * i);
            }
        }

#pragma unroll
        for (int ks = 0; ks < 4; ks++) {
            int kk = ks * 8;
            uint32_t bf[4][2];
#pragma unroll
            for (int nt = 0; nt < 4; nt++) {
                int n = wn * 32 + nt * 8 + gid;
                bf[nt][0] = __float_as_uint(Bs[n * GPAD + kk + tig]);
                bf[nt][1] = __float_as_uint(Bs[n * GPAD + kk + tig + 4]);
            }
#pragma unroll
            for (int mt = 0; mt < 4; mt++) {
                int m = wm * 64 + mt * 16;
                uint32_t af[4];
                af[0] = __float_as_uint(As[(m + gid) * GPAD + kk + tig]);
                af[1] = __float_as_uint(As[(m + gid + 8) * GPAD + kk + tig]);
                af[2] = __float_as_uint(As[(m + gid) * GPAD + kk + tig + 4]);
                af[3] = __float_as_uint(As[(m + gid + 8) * GPAD + kk + tig + 4]);
#pragma unroll
                for (int nt = 0; nt < 4; nt++)
                    mma_tf32(acc[mt][nt], af, bf[nt]);
            }
        }
        __syncthreads();
    }

    // epilogue
#pragma unroll
    for (int mt = 0; mt < 4; mt++) {
#pragma unroll
        for (int nt = 0; nt < 4; nt++) {
            int row0 = bm * 128 + wm * 64 + mt * 16 + gid;
            int col  = bn * 128 + wn * 32 + nt * 8 + 2 * tig;
            float v[4];
#pragma unroll
            for (int q = 0; q < 4; q++) v[q] = acc[mt][nt][q];
            if (bias) {
                float b0 = bias[col], b1 = bias[col + 1];
                v[0] += b0; v[1] += b1; v[2] += b0; v[3] += b1;
            }
            if (ACT == 1) {
#pragma unroll
                for (int q = 0; q < 4; q++) v[q] = v[q] > 0.f ? v[q] : 0.f;
            } else if (ACT == 2) {
#pragma unroll
                for (int q = 0; q < 4; q++) v[q] = 1.f / (1.f + expf(-v[q]));
            }
            *(float2*)&C[(size_t)row0 * N + col]       = make_float2(v[0], v[1]);
            *(float2*)&C[(size_t)(row0 + 8) * N + col] = make_float2(v[2], v[3]);
        }
    }
}

// ---------------- GRU recurrence: R6 structure + targeted trims ------------
// Proven pieces kept: smem h staging (256 threads x 2 ldcg), throttled
// volatile spin with nanosleep. Changes vs R6:
//   __threadfence + volatile flag store  ->  __syncwarp + st.release.gpu
//   final __syncthreads dropped (gates+flag all in warp0)
//   gi in gate-thread registers (no gi_s smem)
//   out[] store moved after the flag release (off critical path)
__device__ __forceinline__ void st_release(int* p, int v) {
    asm volatile("st.release.gpu.b32 [%0], %1;" :: "l"(p), "r"(v) : "memory");
}

__global__ void __launch_bounds__(256, 1) k_gru(
    const float* __restrict__ whhf, const float* __restrict__ whhb,
    const float* __restrict__ bhhf, const float* __restrict__ bhhb)
{
    int dir = blockIdx.y;
    int b   = blockIdx.x;
    const float* gi  = g_gi[dir];
    float*       out = g_dirout[dir];
    const float* whh = dir ? whhb : whhf;
    const float* bhh = dir ? bhhb : bhhf;
    int i0 = b * SLICE;
    int tid = threadIdx.x, lane = tid & 31, warp = tid >> 5;
    int* flags = g_flag[dir];

    __shared__ float h_s[HID];
    __shared__ float dot_s[NROW];

    // weights: thread (warp, lane) owns rows q = warp*6 + r, cols lane + 32*m
    float w[6][16];
#pragma unroll
    for (int r = 0; r < 6; r++) {
        int q = warp * 6 + r;
        int grow = (q / SLICE) * HID + i0 + (q % SLICE);
#pragma unroll
        for (int m = 0; m < 16; m++)
            w[r][m] = whh[(size_t)grow * HID + lane + 32 * m];
    }

    // gate-thread private state (tid < 16 only)
    float hprev = 0.f, bhr = 0.f, bhz = 0.f, bhn = 0.f;
    if (tid < SLICE) {
        bhr = bhh[0 * HID + i0 + tid];
        bhz = bhh[1 * HID + i0 + tid];
        bhn = bhh[2 * HID + i0 + tid];
    }
    __syncthreads();

    for (int t = 0; t < LSEQ; t++) {
        int tt = dir ? (LSEQ - 1 - t) : t;

        // gate threads prefetch gi for this step (latency hidden by spin)
        float gir = 0.f, giz = 0.f, gin = 0.f;
        if (tid < SLICE) {
            const float* g = gi + (size_t)tt * TH3 + i0 + tid;
            gir = __ldg(g);
            giz = __ldg(g + HID);
            gin = __ldg(g + 2 * HID);
        }

        // throttled spin on the 32-flag line (warp0), as in R6
        if (t > 0) {
            if (tid < 32) {
                while (1) {
                    int f = *(volatile int*)&flags[tid];
                    if (__all_sync(0xffffffffu, f >= t - 1)) break;
                    __nanosleep(40);
                }
            }
            __syncthreads();
        }

        // stage h_prev through smem: 2 ldcg per thread (minimal L2 traffic)
        const float* hg = g_h[dir][t & 1];
        for (int k = tid; k < HID; k += 256) h_s[k] = __ldcg(&hg[k]);
        __syncthreads();

        float hv[16];
#pragma unroll
        for (int m = 0; m < 16; m++) hv[m] = h_s[lane + 32 * m];

        float acc[6];
#pragma unroll
        for (int r = 0; r < 6; r++) {
            float a = 0.f;
#pragma unroll
            for (int m = 0; m < 16; m++) a = fmaf(w[r][m], hv[m], a);
            acc[r] = a;
        }
#pragma unroll
        for (int r = 0; r < 6; r++) {
#pragma unroll
            for (int off = 16; off > 0; off >>= 1)
                acc[r] += __shfl_down_sync(0xffffffffu, acc[r], off);
        }
        if (lane == 0) {
#pragma unroll
            for (int r = 0; r < 6; r++) dot_s[warp * 6 + r] = acc[r];
        }
        __syncthreads();

        // warp0: gates, publish h, release flag; out store off critical path.
        // warps 1-7 run ahead to the next spin barrier; dot_s/h_s are not
        // rewritten until warp0 joins that barrier, so no WAR hazard.
        if (warp == 0) {
            float hnew = 0.f;
            int i = i0 + tid;
            if (tid < SLICE) {
                float hr = dot_s[tid]             + bhr;
                float hz = dot_s[SLICE + tid]     + bhz;
                float hn = dot_s[2 * SLICE + tid] + bhn;
                float rg = 1.f / (1.f + expf(-(gir + hr)));
                float zg = 1.f / (1.f + expf(-(giz + hz)));
                float ng = tanhf(gin + rg * hn);
                hnew = (1.f - zg) * ng + zg * hprev;
                hprev = hnew;
                g_h[dir][(t + 1) & 1][i] = hnew;
            }
            __syncwarp();                              // order h stores before flag
            if (lane == 0) st_release(&flags[b], t);   // release: h visible first
            if (tid < SLICE) out[(size_t)tt * HID + i] = hnew;
        }
    }
}

// ---------------- KAN feature expansion ------------------------------------
__device__ __forceinline__ void kan_feats(float x, float* f) {
    f[0] = x / (1.f + expf(-x));   // silu
    float b[11];
#pragma unroll
    for (int j = 0; j < 11; j++) {
        float gj  = 0.4f * (float)(j - 3) - 1.0f;
        float gj1 = 0.4f * (float)(j - 2) - 1.0f;
        b[j] = (x >= gj && x < gj1) ? 1.f : 0.f;
    }
#pragma unroll
    for (int k = 1; k <= 3; k++) {
#pragma unroll
        for (int j = 0; j < 11; j++) {
            if (j + k < 11) {
                float gj   = 0.4f * (float)(j - 3)     - 1.f;
                float gjk  = 0.4f * (float)(j + k - 3) - 1.f;
                float gj1  = 0.4f * (float)(j - 2)     - 1.f;
                float gjk1 = 0.4f * (float)(j + k - 2) - 1.f;
                b[j] = (x - gj) / (gjk - gj) * b[j]
                     + (gjk1 - x) / (gjk1 - gj1) * b[j + 1];
            }
        }
    }
#pragma unroll
    for (int q = 0; q < 8; q++) f[1 + q] = b[q];
}

__global__ void k_expand1(float* __restrict__ A) {
    int idx = blockIdx.x * 256 + threadIdx.x;   // n*1024 + i
    int n = idx >> 10, i = idx & 1023;
    float x = (i < HID) ? g_dirout[0][n * HID + i]
                        : g_dirout[1][n * HID + (i - HID)];
    float f[9]; kan_feats(x, f);
    float* dst = A + (size_t)n * KF1 + i * 9;
#pragma unroll
    for (int c = 0; c < 9; c++) dst[c] = f[c];
}

__global__ void k_expand2(const float* __restrict__ a1, float* __restrict__ A) {
    int idx = blockIdx.x * 256 + threadIdx.x;   // n*512 + i
    float x = a1[idx];
    int n = idx >> 9, i = idx & 511;
    float f[9]; kan_feats(x, f);
    float* dst = A + (size_t)n * KF2 + i * 9;
#pragma unroll
    for (int c = 0; c < 9; c++) dst[c] = f[c];
}

__global__ void k_buildW(const float* __restrict__ bw, const float* __restrict__ sw,
                         const float* __restrict__ sc, float* __restrict__ W, int INF) {
    int idx = blockIdx.x * 256 + threadIdx.x;
    if (idx >= HID * INF) return;
    int i = idx % INF;
    int o = idx / INF;
    float s = sc[idx];
    float* dst = W + (size_t)o * INF * 9 + i * 9;
    dst[0] = bw[idx];
#pragma unroll
    for (int q = 0; q < 8; q++) dst[1 + q] = sw[(size_t)idx * 8 + q] * s;
}

// ---------------- final reduction y = a2^T p -------------------------------
__global__ void k_ypart(const float* __restrict__ p) {
    int bb = blockIdx.x;
    int o  = threadIdx.x;
    float acc = 0.f;
    int n0 = bb * 128;
#pragma unroll 4
    for (int n = n0; n < n0 + 128; n++)
        acc = fmaf(g_a2[(size_t)n * HID + o], p[n], acc);
    g_yp[bb][o] = acc;
}

__global__ void k_yfinal(float* __restrict__ y) {
    int o = blockIdx.x * 256 + threadIdx.x;
    float acc = 0.f;
#pragma unroll
    for (int c = 0; c < 32; c++) acc += g_yp[c][o];
    y[o] = acc;
}

// ---------------- launch ---------------------------------------------------
extern "C" void kernel_launch(void* const* d_in, const int* in_sizes, int n_in,
                              void* d_out, int out_size) {
    const float* h    = (const float*)d_in[0];
    const float* p    = (const float*)d_in[1];
    const float* wihf = (const float*)d_in[2];
    const float* whhf = (const float*)d_in[3];
    const float* bihf = (const float*)d_in[4];
    const float* bhhf = (const float*)d_in[5];
    const float* wihb = (const float*)d_in[6];
    const float* whhb = (const float*)d_in[7];
    const float* bihb = (const float*)d_in[8];
    const float* bhhb = (const float*)d_in[9];
    const float* bw1  = (const float*)d_in[10];
    const float* sw1  = (const float*)d_in[11];
    const float* sc1  = (const float*)d_in[12];
    const float* bw2  = (const float*)d_in[13];
    const float* sw2  = (const float*)d_in[14];
    const float* sc2  = (const float*)d_in[15];
    float* out = (float*)d_out;     // [0:512) = y, [512:) = a_1 (L,HID)

    float *gi_base, *A1, *W1, *A2, *W2, *a2;
    cudaGetSymbolAddress((void**)&gi_base, g_gi);
    cudaGetSymbolAddress((void**)&A1, g_A1);
    cudaGetSymbolAddress((void**)&W1, g_W1);
    cudaGetSymbolAddress((void**)&A2, g_A2);
    cudaGetSymbolAddress((void**)&W2, g_W2);
    cudaGetSymbolAddress((void**)&a2, g_a2);
    float* gi_f = gi_base;
    float* gi_b = gi_base + (size_t)LSEQ * TH3;

    k_init<<<8, 256>>>();

    // input-gate GEMMs: gi = h @ w_ih^T + b_ih
    dim3 ggi(TH3 / 128, LSEQ / 128);
    k_gemm<0><<<ggi, 256>>>(h, wihf, bihf, gi_f, LSEQ, TH3, HID);
    k_gemm<0><<<ggi, 256>>>(h, wihb, bihb, gi_b, LSEQ, TH3, HID);

    // weight expansion for both KAN layers (independent of GRU output)
    k_buildW<<<(HID * 1024 + 255) / 256, 256>>>(bw1, sw1, sc1, W1, 1024);
    k_buildW<<<(HID * HID + 255) / 256, 256>>>(bw2, sw2, sc2, W2, HID);

    // recurrence, both directions concurrently
    k_gru<<<dim3(GB, 2), 256>>>(whhf, whhb, bhhf, bhhb);

    // KAN layer 1
    k_expand1<<<(LSEQ * 1024) / 256, 256>>>(A1);
    k_gemm<1><<<dim3(HID / 128, LSEQ / 128), 256>>>(A1, W1, nullptr, out + HID, LSEQ, HID, KF1);

    // KAN layer 2
    k_expand2<<<(LSEQ * HID) / 256, 256>>>(out + HID, A2);
    k_gemm<2><<<dim3(HID / 128, LSEQ / 128), 256>>>(A2, W2, nullptr, a2, LSEQ, HID, KF2);

    // y = a2^T p (deterministic two-stage reduction)
    k_ypart<<<32, 512>>>(p);
    k_yfinal<<<2, 256>>>(out);
}

// round 9
// speedup vs baseline: 1.3915x; 1.1753x over previous
#include <cuda_runtime.h>
#include <cstdint>
#include <cstdio>

#define LSEQ 4096
#define HID  512
#define TH3  1536      // 3*HID
#define GB   32        // blocks per GRU direction
#define SLICE 16       // HID / GB
#define NROW 48        // 3*SLICE rows of w_hh per block
#define KF1  9216      // 1024 * 9 augmented K for KAN layer 1
#define KF2  4608      // 512 * 9  augmented K for KAN layer 2

// ---------------- scratch (device globals; no allocation allowed) ----------
__device__ float g_gi[2][LSEQ * TH3];        // input gates, fwd/bwd
__device__ float g_dirout[2][LSEQ * HID];    // GRU outputs per direction
__device__ float g_A1[LSEQ * KF1];           // augmented features KAN1
__device__ float g_W1[HID * KF1];            // augmented weights  KAN1
__device__ float g_A2[LSEQ * KF2];
__device__ float g_W2[HID * KF2];
__device__ float g_a2[LSEQ * HID];           // sigmoid output of KAN2
// tagged hidden state: word = ((uint64)tag << 32) | float_bits(h).
// buffer parity = tag & 1. 8-byte aligned stores are atomic -> no fences.
__device__ unsigned long long g_hx[2][2][HID];   // [dir][parity][i]
__device__ float g_yp[32][HID];              // partial sums for final reduction

// ---------------- init: reset recurrence state each replay -----------------
__global__ void k_init() {
    int i = blockIdx.x * blockDim.x + threadIdx.x;
    if (i < 2 * 2 * HID) ((unsigned long long*)g_hx)[i] = 0ULL;  // h=0, tag=0
}

// ---------------- TF32 tensor-core GEMM (unchanged, proven) ----------------
#define GPAD 36

__device__ __forceinline__ uint32_t to_tf32(float x) {
    uint32_t r;
    asm("cvt.rna.tf32.f32 %0, %1;" : "=r"(r) : "f"(x));   // tf32 dest is .b32
    return r;
}
__device__ __forceinline__ float to_tf32f(float x) {
    return __uint_as_float(to_tf32(x));
}

__device__ __forceinline__ void mma_tf32(float* c, const uint32_t* a, const uint32_t* b) {
    asm volatile(
        "mma.sync.aligned.m16n8k8.row.col.f32.tf32.tf32.f32 "
        "{%0,%1,%2,%3}, {%4,%5,%6,%7}, {%8,%9}, {%0,%1,%2,%3};"
        : "+f"(c[0]), "+f"(c[1]), "+f"(c[2]), "+f"(c[3])
        : "r"(a[0]), "r"(a[1]), "r"(a[2]), "r"(a[3]), "r"(b[0]), "r"(b[1]));
}

template <int ACT>
__global__ void __launch_bounds__(256, 1) k_gemm(
    const float* __restrict__ A, const float* __restrict__ B,
    const float* __restrict__ bias, float* __restrict__ C,
    int M, int N, int K)
{
    __shared__ float As[128 * GPAD];
    __shared__ float Bs[128 * GPAD];
    int tid = threadIdx.x, lane = tid & 31, warp = tid >> 5;
    int wm = warp >> 2, wn = warp & 3;          // warp grid 2 (M) x 4 (N)
    int gid = lane >> 2, tig = lane & 3;
    int bm = blockIdx.y, bn = blockIdx.x;
    const float* Ab = A + (size_t)bm * 128 * K;
    const float* Bb = B + (size_t)bn * 128 * K;

    int r = tid >> 1, seg = (tid & 1) * 16;     // staging: row r, 16 cols

    float4 sa[4], sb[4];
    float acc[4][4][4];
#pragma unroll
    for (int mt = 0; mt < 4; mt++)
#pragma unroll
        for (int nt = 0; nt < 4; nt++)
#pragma unroll
            for (int q = 0; q < 4; q++) acc[mt][nt][q] = 0.f;

    // prefetch slab 0
#pragma unroll
    for (int i = 0; i < 4; i++) {
        sa[i] = *(const float4*)(Ab + (size_t)r * K + seg + 4 * i);
        sb[i] = *(const float4*)(Bb + (size_t)r * K + seg + 4 * i);
    }

    for (int k0 = 0; k0 < K; k0 += 32) {
        // stage regs -> smem (tf32-rounded)
#pragma unroll
        for (int i = 0; i < 4; i++) {
            float4 a = sa[i], b = sb[i];
            a.x = to_tf32f(a.x); a.y = to_tf32f(a.y);
            a.z = to_tf32f(a.z); a.w = to_tf32f(a.w);
            b.x = to_tf32f(b.x); b.y = to_tf32f(b.y);
            b.z = to_tf32f(b.z); b.w = to_tf32f(b.w);
            *(float4*)&As[r * GPAD + seg + 4 * i] = a;
            *(float4*)&Bs[r * GPAD + seg + 4 * i] = b;
        }
        __syncthreads();

        // prefetch next slab
        if (k0 + 32 < K) {
#pragma unroll
            for (int i = 0; i < 4; i++) {
                sa[i] = *(const float4*)(Ab + (size_t)r * K + k0 + 32 + seg + 4 * i);
                sb[i] = *(const float4*)(Bb + (size_t)r * K + k0 + 32 + seg + 4 * i);
            }
        }

#pragma unroll
        for (int ks = 0; ks < 4; ks++) {
            int kk = ks * 8;
            uint32_t bf[4][2];
#pragma unroll
            for (int nt = 0; nt < 4; nt++) {
                int n = wn * 32 + nt * 8 + gid;
                bf[nt][0] = __float_as_uint(Bs[n * GPAD + kk + tig]);
                bf[nt][1] = __float_as_uint(Bs[n * GPAD + kk + tig + 4]);
            }
#pragma unroll
            for (int mt = 0; mt < 4; mt++) {
                int m = wm * 64 + mt * 16;
                uint32_t af[4];
                af[0] = __float_as_uint(As[(m + gid) * GPAD + kk + tig]);
                af[1] = __float_as_uint(As[(m + gid + 8) * GPAD + kk + tig]);
                af[2] = __float_as_uint(As[(m + gid) * GPAD + kk + tig + 4]);
                af[3] = __float_as_uint(As[(m + gid + 8) * GPAD + kk + tig + 4]);
#pragma unroll
                for (int nt = 0; nt < 4; nt++)
                    mma_tf32(acc[mt][nt], af, bf[nt]);
            }
        }
        __syncthreads();
    }

    // epilogue
#pragma unroll
    for (int mt = 0; mt < 4; mt++) {
#pragma unroll
        for (int nt = 0; nt < 4; nt++) {
            int row0 = bm * 128 + wm * 64 + mt * 16 + gid;
            int col  = bn * 128 + wn * 32 + nt * 8 + 2 * tig;
            float v[4];
#pragma unroll
            for (int q = 0; q < 4; q++) v[q] = acc[mt][nt][q];
            if (bias) {
                float b0 = bias[col], b1 = bias[col + 1];
                v[0] += b0; v[1] += b1; v[2] += b0; v[3] += b1;
            }
            if (ACT == 1) {
#pragma unroll
                for (int q = 0; q < 4; q++) v[q] = v[q] > 0.f ? v[q] : 0.f;
            } else if (ACT == 2) {
#pragma unroll
                for (int q = 0; q < 4; q++) v[q] = 1.f / (1.f + expf(-v[q]));
            }
            *(float2*)&C[(size_t)row0 * N + col]       = make_float2(v[0], v[1]);
            *(float2*)&C[(size_t)(row0 + 8) * N + col] = make_float2(v[2], v[3]);
        }
    }
}

// ---------------- GRU recurrence: tagged-word handoff ----------------------
// No flags, no fences. Producer stores (tag=t+1, h) as one atomic 8B word;
// consumers poll the words themselves — the h load IS the sync. Double
// buffer by parity prevents overwrite of a still-needed step.
__global__ void __launch_bounds__(256, 1) k_gru(
    const float* __restrict__ whhf, const float* __restrict__ whhb,
    const float* __restrict__ bhhf, const float* __restrict__ bhhb)
{
    int dir = blockIdx.y;
    int b   = blockIdx.x;
    const float* gi  = g_gi[dir];
    float*       out = g_dirout[dir];
    const float* whh = dir ? whhb : whhf;
    const float* bhh = dir ? bhhb : bhhf;
    int i0 = b * SLICE;
    int tid = threadIdx.x, lane = tid & 31, warp = tid >> 5;

    __shared__ float h_s[HID];
    __shared__ float dot_s[NROW];

    // weights: thread (warp, lane) owns rows q = warp*6 + r, cols lane + 32*m
    float w[6][16];
#pragma unroll
    for (int r = 0; r < 6; r++) {
        int q = warp * 6 + r;
        int grow = (q / SLICE) * HID + i0 + (q % SLICE);
#pragma unroll
        for (int m = 0; m < 16; m++)
            w[r][m] = whh[(size_t)grow * HID + lane + 32 * m];
    }

    // gate-thread private state (tid < 16 only)
    float hprev = 0.f, bhr = 0.f, bhz = 0.f, bhn = 0.f;
    if (tid < SLICE) {
        bhr = bhh[0 * HID + i0 + tid];
        bhz = bhh[1 * HID + i0 + tid];
        bhn = bhh[2 * HID + i0 + tid];
    }
    __syncthreads();

    for (int t = 0; t < LSEQ; t++) {
        int tt = dir ? (LSEQ - 1 - t) : t;

        // gate threads prefetch gi for this step (latency hidden by poll)
        float gir = 0.f, giz = 0.f, gin = 0.f;
        if (tid < SLICE) {
            const float* g = gi + (size_t)tt * TH3 + i0 + tid;
            gir = __ldg(g);
            giz = __ldg(g + HID);
            gin = __ldg(g + 2 * HID);
        }

        // poll tagged h words directly: each thread owns words tid, tid+256
        const unsigned long long* hx = g_hx[dir][t & 1];
        unsigned tg = (unsigned)t;
        {
            unsigned long long v0 = __ldcg(&hx[tid]);
            while ((unsigned)(v0 >> 32) != tg) { __nanosleep(20); v0 = __ldcg(&hx[tid]); }
            h_s[tid] = __uint_as_float((unsigned)v0);
            unsigned long long v1 = __ldcg(&hx[tid + 256]);
            while ((unsigned)(v1 >> 32) != tg) { __nanosleep(20); v1 = __ldcg(&hx[tid + 256]); }
            h_s[tid + 256] = __uint_as_float((unsigned)v1);
        }
        __syncthreads();

        float hv[16];
#pragma unroll
        for (int m = 0; m < 16; m++) hv[m] = h_s[lane + 32 * m];

        float acc[6];
#pragma unroll
        for (int r = 0; r < 6; r++) {
            float a = 0.f;
#pragma unroll
            for (int m = 0; m < 16; m++) a = fmaf(w[r][m], hv[m], a);
            acc[r] = a;
        }
#pragma unroll
        for (int r = 0; r < 6; r++) {
#pragma unroll
            for (int off = 16; off > 0; off >>= 1)
                acc[r] += __shfl_down_sync(0xffffffffu, acc[r], off);
        }
        if (lane == 0) {
#pragma unroll
            for (int r = 0; r < 6; r++) dot_s[warp * 6 + r] = acc[r];
        }
        __syncthreads();

        // warp0: gates + tagged publish (atomic 8B word, no fence needed).
        // warps 1-7 run ahead to next poll; their words can't be ready until
        // this publish lands, and dot_s isn't rewritten until warp0 rejoins
        // the next barrier -> no WAR hazard.
        if (warp == 0) {
            if (tid < SLICE) {
                int i = i0 + tid;
                float hr = dot_s[tid]             + bhr;
                float hz = dot_s[SLICE + tid]     + bhz;
                float hn = dot_s[2 * SLICE + tid] + bhn;
                float rg = 1.f / (1.f + expf(-(gir + hr)));
                float zg = 1.f / (1.f + expf(-(giz + hz)));
                float ng = tanhf(gin + rg * hn);
                float hnew = (1.f - zg) * ng + zg * hprev;
                hprev = hnew;
                unsigned long long pv =
                    ((unsigned long long)(unsigned)(t + 1) << 32) |
                    (unsigned long long)__float_as_uint(hnew);
                __stcg(&g_hx[dir][(t + 1) & 1][i], pv);
                out[(size_t)tt * HID + i] = hnew;   // off critical path
            }
        }
    }
}

// ---------------- KAN feature expansion ------------------------------------
__device__ __forceinline__ void kan_feats(float x, float* f) {
    f[0] = x / (1.f + expf(-x));   // silu
    float b[11];
#pragma unroll
    for (int j = 0; j < 11; j++) {
        float gj  = 0.4f * (float)(j - 3) - 1.0f;
        float gj1 = 0.4f * (float)(j - 2) - 1.0f;
        b[j] = (x >= gj && x < gj1) ? 1.f : 0.f;
    }
#pragma unroll
    for (int k = 1; k <= 3; k++) {
#pragma unroll
        for (int j = 0; j < 11; j++) {
            if (j + k < 11) {
                float gj   = 0.4f * (float)(j - 3)     - 1.f;
                float gjk  = 0.4f * (float)(j + k - 3) - 1.f;
                float gj1  = 0.4f * (float)(j - 2)     - 1.f;
                float gjk1 = 0.4f * (float)(j + k - 2) - 1.f;
                b[j] = (x - gj) / (gjk - gj) * b[j]
                     + (gjk1 - x) / (gjk1 - gj1) * b[j + 1];
            }
        }
    }
#pragma unroll
    for (int q = 0; q < 8; q++) f[1 + q] = b[q];
}

__global__ void k_expand1(float* __restrict__ A) {
    int idx = blockIdx.x * 256 + threadIdx.x;   // n*1024 + i
    int n = idx >> 10, i = idx & 1023;
    float x = (i < HID) ? g_dirout[0][n * HID + i]
                        : g_dirout[1][n * HID + (i - HID)];
    float f[9]; kan_feats(x, f);
    float* dst = A + (size_t)n * KF1 + i * 9;
#pragma unroll
    for (int c = 0; c < 9; c++) dst[c] = f[c];
}

__global__ void k_expand2(const float* __restrict__ a1, float* __restrict__ A) {
    int idx = blockIdx.x * 256 + threadIdx.x;   // n*512 + i
    float x = a1[idx];
    int n = idx >> 9, i = idx & 511;
    float f[9]; kan_feats(x, f);
    float* dst = A + (size_t)n * KF2 + i * 9;
#pragma unroll
    for (int c = 0; c < 9; c++) dst[c] = f[c];
}

__global__ void k_buildW(const float* __restrict__ bw, const float* __restrict__ sw,
                         const float* __restrict__ sc, float* __restrict__ W, int INF) {
    int idx = blockIdx.x * 256 + threadIdx.x;
    if (idx >= HID * INF) return;
    int i = idx % INF;
    int o = idx / INF;
    float s = sc[idx];
    float* dst = W + (size_t)o * INF * 9 + i * 9;
    dst[0] = bw[idx];
#pragma unroll
    for (int q = 0; q < 8; q++) dst[1 + q] = sw[(size_t)idx * 8 + q] * s;
}

// ---------------- final reduction y = a2^T p -------------------------------
__global__ void k_ypart(const float* __restrict__ p) {
    int bb = blockIdx.x;
    int o  = threadIdx.x;
    float acc = 0.f;
    int n0 = bb * 128;
#pragma unroll 4
    for (int n = n0; n < n0 + 128; n++)
        acc = fmaf(g_a2[(size_t)n * HID + o], p[n], acc);
    g_yp[bb][o] = acc;
}

__global__ void k_yfinal(float* __restrict__ y) {
    int o = blockIdx.x * 256 + threadIdx.x;
    float acc = 0.f;
#pragma unroll
    for (int c = 0; c < 32; c++) acc += g_yp[c][o];
    y[o] = acc;
}

// ---------------- launch ---------------------------------------------------
extern "C" void kernel_launch(void* const* d_in, const int* in_sizes, int n_in,
                              void* d_out, int out_size) {
    const float* h    = (const float*)d_in[0];
    const float* p    = (const float*)d_in[1];
    const float* wihf = (const float*)d_in[2];
    const float* whhf = (const float*)d_in[3];
    const float* bihf = (const float*)d_in[4];
    const float* bhhf = (const float*)d_in[5];
    const float* wihb = (const float*)d_in[6];
    const float* whhb = (const float*)d_in[7];
    const float* bihb = (const float*)d_in[8];
    const float* bhhb = (const float*)d_in[9];
    const float* bw1  = (const float*)d_in[10];
    const float* sw1  = (const float*)d_in[11];
    const float* sc1  = (const float*)d_in[12];
    const float* bw2  = (const float*)d_in[13];
    const float* sw2  = (const float*)d_in[14];
    const float* sc2  = (const float*)d_in[15];
    float* out = (float*)d_out;     // [0:512) = y, [512:) = a_1 (L,HID)

    float *gi_base, *A1, *W1, *A2, *W2, *a2;
    cudaGetSymbolAddress((void**)&gi_base, g_gi);
    cudaGetSymbolAddress((void**)&A1, g_A1);
    cudaGetSymbolAddress((void**)&W1, g_W1);
    cudaGetSymbolAddress((void**)&A2, g_A2);
    cudaGetSymbolAddress((void**)&W2, g_W2);
    cudaGetSymbolAddress((void**)&a2, g_a2);
    float* gi_f = gi_base;
    float* gi_b = gi_base + (size_t)LSEQ * TH3;

    k_init<<<8, 256>>>();

    // input-gate GEMMs: gi = h @ w_ih^T + b_ih
    dim3 ggi(TH3 / 128, LSEQ / 128);
    k_gemm<0><<<ggi, 256>>>(h, wihf, bihf, gi_f, LSEQ, TH3, HID);
    k_gemm<0><<<ggi, 256>>>(h, wihb, bihb, gi_b, LSEQ, TH3, HID);

    // weight expansion for both KAN layers (independent of GRU output)
    k_buildW<<<(HID * 1024 + 255) / 256, 256>>>(bw1, sw1, sc1, W1, 1024);
    k_buildW<<<(HID * HID + 255) / 256, 256>>>(bw2, sw2, sc2, W2, HID);

    // recurrence, both directions concurrently
    k_gru<<<dim3(GB, 2), 256>>>(whhf, whhb, bhhf, bhhb);

    // KAN layer 1
    k_expand1<<<(LSEQ * 1024) / 256, 256>>>(A1);
    k_gemm<1><<<dim3(HID / 128, LSEQ / 128), 256>>>(A1, W1, nullptr, out + HID, LSEQ, HID, KF1);

    // KAN layer 2
    k_expand2<<<(LSEQ * HID) / 256, 256>>>(out + HID, A2);
    k_gemm<2><<<dim3(HID / 128, LSEQ / 128), 256>>>(A2, W2, nullptr, a2, LSEQ, HID, KF2);

    // y = a2^T p (deterministic two-stage reduction)
    k_ypart<<<32, 512>>>(p);
    k_yfinal<<<2, 256>>>(out);
}

// round 11
// speedup vs baseline: 1.6638x; 1.1957x over previous
#include <cuda_runtime.h>
#include <cstdint>
#include <cstdio>

#define LSEQ 4096
#define HID  512
#define TH3  1536      // 3*HID
#define GB   64        // blocks per GRU direction
#define SLICE 8        // HID / GB
#define NROW 24        // 3*SLICE rows of w_hh per block
#define KF1  9216      // 1024 * 9 augmented K for KAN layer 1
#define KF2  4608      // 512 * 9  augmented K for KAN layer 2

// ---------------- scratch (device globals; no allocation allowed) ----------
__device__ float g_gi[2][LSEQ * TH3];        // input gates, fwd/bwd
__device__ float g_dirout[2][LSEQ * HID];    // GRU outputs per direction
__device__ float g_A1[LSEQ * KF1];           // augmented features KAN1
__device__ float g_W1[HID * KF1];            // augmented weights  KAN1
__device__ float g_A2[LSEQ * KF2];
__device__ float g_W2[HID * KF2];
__device__ float g_a2[LSEQ * HID];           // sigmoid output of KAN2
// tagged hidden state: word = ((uint64)tag << 32) | float_bits(h).
// buffer parity = tag & 1. 8-byte aligned stores are atomic -> no fences.
__device__ unsigned long long g_hx[2][2][HID];   // [dir][parity][i]
__device__ float g_yp[32][HID];              // partial sums for final reduction

// ---------------- init: reset recurrence state each replay -----------------
__global__ void k_init() {
    int i = blockIdx.x * blockDim.x + threadIdx.x;
    if (i < 2 * 2 * HID) ((unsigned long long*)g_hx)[i] = 0ULL;  // h=0, tag=0
}

// ---------------- TF32 tensor-core GEMM (unchanged, proven) ----------------
#define GPAD 36

__device__ __forceinline__ uint32_t to_tf32(float x) {
    uint32_t r;
    asm("cvt.rna.tf32.f32 %0, %1;" : "=r"(r) : "f"(x));   // tf32 dest is .b32
    return r;
}
__device__ __forceinline__ float to_tf32f(float x) {
    return __uint_as_float(to_tf32(x));
}

__device__ __forceinline__ void mma_tf32(float* c, const uint32_t* a, const uint32_t* b) {
    asm volatile(
        "mma.sync.aligned.m16n8k8.row.col.f32.tf32.tf32.f32 "
        "{%0,%1,%2,%3}, {%4,%5,%6,%7}, {%8,%9}, {%0,%1,%2,%3};"
        : "+f"(c[0]), "+f"(c[1]), "+f"(c[2]), "+f"(c[3])
        : "r"(a[0]), "r"(a[1]), "r"(a[2]), "r"(a[3]), "r"(b[0]), "r"(b[1]));
}

template <int ACT>
__global__ void __launch_bounds__(256, 1) k_gemm(
    const float* __restrict__ A, const float* __restrict__ B,
    const float* __restrict__ bias, float* __restrict__ C,
    int M, int N, int K)
{
    __shared__ float As[128 * GPAD];
    __shared__ float Bs[128 * GPAD];
    int tid = threadIdx.x, lane = tid & 31, warp = tid >> 5;
    int wm = warp >> 2, wn = warp & 3;          // warp grid 2 (M) x 4 (N)
    int gid = lane >> 2, tig = lane & 3;
    int bm = blockIdx.y, bn = blockIdx.x;
    const float* Ab = A + (size_t)bm * 128 * K;
    const float* Bb = B + (size_t)bn * 128 * K;

    int r = tid >> 1, seg = (tid & 1) * 16;     // staging: row r, 16 cols

    float4 sa[4], sb[4];
    float acc[4][4][4];
#pragma unroll
    for (int mt = 0; mt < 4; mt++)
#pragma unroll
        for (int nt = 0; nt < 4; nt++)
#pragma unroll
            for (int q = 0; q < 4; q++) acc[mt][nt][q] = 0.f;

    // prefetch slab 0
#pragma unroll
    for (int i = 0; i < 4; i++) {
        sa[i] = *(const float4*)(Ab + (size_t)r * K + seg + 4 * i);
        sb[i] = *(const float4*)(Bb + (size_t)r * K + seg + 4 * i);
    }

    for (int k0 = 0; k0 < K; k0 += 32) {
        // stage regs -> smem (tf32-rounded)
#pragma unroll
        for (int i = 0; i < 4; i++) {
            float4 a = sa[i], b = sb[i];
            a.x = to_tf32f(a.x); a.y = to_tf32f(a.y);
            a.z = to_tf32f(a.z); a.w = to_tf32f(a.w);
            b.x = to_tf32f(b.x); b.y = to_tf32f(b.y);
            b.z = to_tf32f(b.z); b.w = to_tf32f(b.w);
            *(float4*)&As[r * GPAD + seg + 4 * i] = a;
            *(float4*)&Bs[r * GPAD + seg + 4 * i] = b;
        }
        __syncthreads();

        // prefetch next slab
        if (k0 + 32 < K) {
#pragma unroll
            for (int i = 0; i < 4; i++) {
                sa[i] = *(const float4*)(Ab + (size_t)r * K + k0 + 32 + seg + 4 * i);
                sb[i] = *(const float4*)(Bb + (size_t)r * K + k0 + 32 + seg + 4 * i);
            }
        }

#pragma unroll
        for (int ks = 0; ks < 4; ks++) {
            int kk = ks * 8;
            uint32_t bf[4][2];
#pragma unroll
            for (int nt = 0; nt < 4; nt++) {
                int n = wn * 32 + nt * 8 + gid;
                bf[nt][0] = __float_as_uint(Bs[n * GPAD + kk + tig]);
                bf[nt][1] = __float_as_uint(Bs[n * GPAD + kk + tig + 4]);
            }
#pragma unroll
            for (int mt = 0; mt < 4; mt++) {
                int m = wm * 64 + mt * 16;
                uint32_t af[4];
                af[0] = __float_as_uint(As[(m + gid) * GPAD + kk + tig]);
                af[1] = __float_as_uint(As[(m + gid + 8) * GPAD + kk + tig]);
                af[2] = __float_as_uint(As[(m + gid) * GPAD + kk + tig + 4]);
                af[3] = __float_as_uint(As[(m + gid + 8) * GPAD + kk + tig + 4]);
#pragma unroll
                for (int nt = 0; nt < 4; nt++)
                    mma_tf32(acc[mt][nt], af, bf[nt]);
            }
        }
        __syncthreads();
    }

    // epilogue
#pragma unroll
    for (int mt = 0; mt < 4; mt++) {
#pragma unroll
        for (int nt = 0; nt < 4; nt++) {
            int row0 = bm * 128 + wm * 64 + mt * 16 + gid;
            int col  = bn * 128 + wn * 32 + nt * 8 + 2 * tig;
            float v[4];
#pragma unroll
            for (int q = 0; q < 4; q++) v[q] = acc[mt][nt][q];
            if (bias) {
                float b0 = bias[col], b1 = bias[col + 1];
                v[0] += b0; v[1] += b1; v[2] += b0; v[3] += b1;
            }
            if (ACT == 1) {
#pragma unroll
                for (int q = 0; q < 4; q++) v[q] = v[q] > 0.f ? v[q] : 0.f;
            } else if (ACT == 2) {
#pragma unroll
                for (int q = 0; q < 4; q++) v[q] = 1.f / (1.f + expf(-v[q]));
            }
            *(float2*)&C[(size_t)row0 * N + col]       = make_float2(v[0], v[1]);
            *(float2*)&C[(size_t)(row0 + 8) * N + col] = make_float2(v[2], v[3]);
        }
    }
}

// ---------------- GRU recurrence: tagged-word handoff, 64 blocks/dir -------
// SLICE=8: each block owns 8 h-indices, 24 w_hh rows -> 48 FMA/thread on the
// critical path (half of R9). Poll issues both loads before checking either.
__global__ void __launch_bounds__(256, 1) k_gru(
    const float* __restrict__ whhf, const float* __restrict__ whhb,
    const float* __restrict__ bhhf, const float* __restrict__ bhhb)
{
    int dir = blockIdx.y;
    int b   = blockIdx.x;
    const float* gi  = g_gi[dir];
    float*       out = g_dirout[dir];
    const float* whh = dir ? whhb : whhf;
    const float* bhh = dir ? bhhb : bhhf;
    int i0 = b * SLICE;
    int tid = threadIdx.x, lane = tid & 31, warp = tid >> 5;

    __shared__ float h_s[HID];
    __shared__ float dot_s[NROW];

    // weights: thread (warp, lane) owns rows q = warp*3 + r, cols lane + 32*m
    float w[3][16];
#pragma unroll
    for (int r = 0; r < 3; r++) {
        int q = warp * 3 + r;
        int grow = (q / SLICE) * HID + i0 + (q % SLICE);
#pragma unroll
        for (int m = 0; m < 16; m++)
            w[r][m] = whh[(size_t)grow * HID + lane + 32 * m];
    }

    // gate-thread private state (tid < 8 only)
    float hprev = 0.f, bhr = 0.f, bhz = 0.f, bhn = 0.f;
    if (tid < SLICE) {
        bhr = bhh[0 * HID + i0 + tid];
        bhz = bhh[1 * HID + i0 + tid];
        bhn = bhh[2 * HID + i0 + tid];
    }
    __syncthreads();

    for (int t = 0; t < LSEQ; t++) {
        int tt = dir ? (LSEQ - 1 - t) : t;

        // gate threads prefetch gi for this step (latency hidden by poll)
        float gir = 0.f, giz = 0.f, gin = 0.f;
        if (tid < SLICE) {
            const float* g = gi + (size_t)tt * TH3 + i0 + tid;
            gir = __ldg(g);
            giz = __ldg(g + HID);
            gin = __ldg(g + 2 * HID);
        }

        // poll tagged h words: each thread owns words tid, tid+256.
        // Both loads issue before either check (overlap the L2 round trips).
        const unsigned long long* hx = g_hx[dir][t & 1];
        unsigned tg = (unsigned)t;
        {
            unsigned long long v0 = __ldcg(&hx[tid]);
            unsigned long long v1 = __ldcg(&hx[tid + 256]);
            while ((unsigned)(v0 >> 32) != tg) { __nanosleep(20); v0 = __ldcg(&hx[tid]); }
            while ((unsigned)(v1 >> 32) != tg) { __nanosleep(20); v1 = __ldcg(&hx[tid + 256]); }
            h_s[tid] = __uint_as_float((unsigned)v0);
            h_s[tid + 256] = __uint_as_float((unsigned)v1);
        }
        __syncthreads();

        float hv[16];
#pragma unroll
        for (int m = 0; m < 16; m++) hv[m] = h_s[lane + 32 * m];

        float acc[3];
#pragma unroll
        for (int r = 0; r < 3; r++) {
            float a = 0.f;
#pragma unroll
            for (int m = 0; m < 16; m++) a = fmaf(w[r][m], hv[m], a);
            acc[r] = a;
        }
#pragma unroll
        for (int r = 0; r < 3; r++) {
#pragma unroll
            for (int off = 16; off > 0; off >>= 1)
                acc[r] += __shfl_down_sync(0xffffffffu, acc[r], off);
        }
        if (lane == 0) {
#pragma unroll
            for (int r = 0; r < 3; r++) dot_s[warp * 3 + r] = acc[r];
        }
        __syncthreads();

        // warp0: gates + tagged publish (atomic 8B word, no fence needed).
        if (warp == 0) {
            if (tid < SLICE) {
                int i = i0 + tid;
                float hr = dot_s[tid]             + bhr;
                float hz = dot_s[SLICE + tid]     + bhz;
                float hn = dot_s[2 * SLICE + tid] + bhn;
                float rg = 1.f / (1.f + expf(-(gir + hr)));
                float zg = 1.f / (1.f + expf(-(giz + hz)));
                float ng = tanhf(gin + rg * hn);
                float hnew = (1.f - zg) * ng + zg * hprev;
                hprev = hnew;
                unsigned long long pv =
                    ((unsigned long long)(unsigned)(t + 1) << 32) |
                    (unsigned long long)__float_as_uint(hnew);
                __stcg(&g_hx[dir][(t + 1) & 1][i], pv);
                out[(size_t)tt * HID + i] = hnew;   // off critical path
            }
        }
    }
}

// ---------------- KAN feature expansion ------------------------------------
__device__ __forceinline__ void kan_feats(float x, float* f) {
    f[0] = x / (1.f + expf(-x));   // silu
    float b[11];
#pragma unroll
    for (int j = 0; j < 11; j++) {
        float gj  = 0.4f * (float)(j - 3) - 1.0f;
        float gj1 = 0.4f * (float)(j - 2) - 1.0f;
        b[j] = (x >= gj && x < gj1) ? 1.f : 0.f;
    }
#pragma unroll
    for (int k = 1; k <= 3; k++) {
#pragma unroll
        for (int j = 0; j < 11; j++) {
            if (j + k < 11) {
                float gj   = 0.4f * (float)(j - 3)     - 1.f;
                float gjk  = 0.4f * (float)(j + k - 3) - 1.f;
                float gj1  = 0.4f * (float)(j - 2)     - 1.f;
                float gjk1 = 0.4f * (float)(j + k - 2) - 1.f;
                b[j] = (x - gj) / (gjk - gj) * b[j]
                     + (gjk1 - x) / (gjk1 - gj1) * b[j + 1];
            }
        }
    }
#pragma unroll
    for (int q = 0; q < 8; q++) f[1 + q] = b[q];
}

__global__ void k_expand1(float* __restrict__ A) {
    int idx = blockIdx.x * 256 + threadIdx.x;   // n*1024 + i
    int n = idx >> 10, i = idx & 1023;
    float x = (i < HID) ? g_dirout[0][n * HID + i]
                        : g_dirout[1][n * HID + (i - HID)];
    float f[9]; kan_feats(x, f);
    float* dst = A + (size_t)n * KF1 + i * 9;
#pragma unroll
    for (int c = 0; c < 9; c++) dst[c] = f[c];
}

__global__ void k_expand2(const float* __restrict__ a1, float* __restrict__ A) {
    int idx = blockIdx.x * 256 + threadIdx.x;   // n*512 + i
    float x = a1[idx];
    int n = idx >> 9, i = idx & 511;
    float f[9]; kan_feats(x, f);
    float* dst = A + (size_t)n * KF2 + i * 9;
#pragma unroll
    for (int c = 0; c < 9; c++) dst[c] = f[c];
}

__global__ void k_buildW(const float* __restrict__ bw, const float* __restrict__ sw,
                         const float* __restrict__ sc, float* __restrict__ W, int INF) {
    int idx = blockIdx.x * 256 + threadIdx.x;
    if (idx >= HID * INF) return;
    int i = idx % INF;
    int o = idx / INF;
    float s = sc[idx];
    float* dst = W + (size_t)o * INF * 9 + i * 9;
    dst[0] = bw[idx];
#pragma unroll
    for (int q = 0; q < 8; q++) dst[1 + q] = sw[(size_t)idx * 8 + q] * s;
}

// ---------------- final reduction y = a2^T p -------------------------------
__global__ void k_ypart(const float* __restrict__ p) {
    int bb = blockIdx.x;
    int o  = threadIdx.x;
    float acc = 0.f;
    int n0 = bb * 128;
#pragma unroll 4
    for (int n = n0; n < n0 + 128; n++)
        acc = fmaf(g_a2[(size_t)n * HID + o], p[n], acc);
    g_yp[bb][o] = acc;
}

__global__ void k_yfinal(float* __restrict__ y) {
    int o = blockIdx.x * 256 + threadIdx.x;
    float acc = 0.f;
#pragma unroll
    for (int c = 0; c < 32; c++) acc += g_yp[c][o];
    y[o] = acc;
}

// ---------------- launch ---------------------------------------------------
extern "C" void kernel_launch(void* const* d_in, const int* in_sizes, int n_in,
                              void* d_out, int out_size) {
    const float* h    = (const float*)d_in[0];
    const float* p    = (const float*)d_in[1];
    const float* wihf = (const float*)d_in[2];
    const float* whhf = (const float*)d_in[3];
    const float* bihf = (const float*)d_in[4];
    const float* bhhf = (const float*)d_in[5];
    const float* wihb = (const float*)d_in[6];
    const float* whhb = (const float*)d_in[7];
    const float* bihb = (const float*)d_in[8];
    const float* bhhb = (const float*)d_in[9];
    const float* bw1  = (const float*)d_in[10];
    const float* sw1  = (const float*)d_in[11];
    const float* sc1  = (const float*)d_in[12];
    const float* bw2  = (const float*)d_in[13];
    const float* sw2  = (const float*)d_in[14];
    const float* sc2  = (const float*)d_in[15];
    float* out = (float*)d_out;     // [0:512) = y, [512:) = a_1 (L,HID)

    float *gi_base, *A1, *W1, *A2, *W2, *a2;
    cudaGetSymbolAddress((void**)&gi_base, g_gi);
    cudaGetSymbolAddress((void**)&A1, g_A1);
    cudaGetSymbolAddress((void**)&W1, g_W1);
    cudaGetSymbolAddress((void**)&A2, g_A2);
    cudaGetSymbolAddress((void**)&W2, g_W2);
    cudaGetSymbolAddress((void**)&a2, g_a2);
    float* gi_f = gi_base;
    float* gi_b = gi_base + (size_t)LSEQ * TH3;

    k_init<<<8, 256>>>();

    // input-gate GEMMs: gi = h @ w_ih^T + b_ih
    dim3 ggi(TH3 / 128, LSEQ / 128);
    k_gemm<0><<<ggi, 256>>>(h, wihf, bihf, gi_f, LSEQ, TH3, HID);
    k_gemm<0><<<ggi, 256>>>(h, wihb, bihb, gi_b, LSEQ, TH3, HID);

    // weight expansion for both KAN layers (independent of GRU output)
    k_buildW<<<(HID * 1024 + 255) / 256, 256>>>(bw1, sw1, sc1, W1, 1024);
    k_buildW<<<(HID * HID + 255) / 256, 256>>>(bw2, sw2, sc2, W2, HID);

    // recurrence, both directions concurrently
    k_gru<<<dim3(GB, 2), 256>>>(whhf, whhb, bhhf, bhhb);

    // KAN layer 1
    k_expand1<<<(LSEQ * 1024) / 256, 256>>>(A1);
    k_gemm<1><<<dim3(HID / 128, LSEQ / 128), 256>>>(A1, W1, nullptr, out + HID, LSEQ, HID, KF1);

    // KAN layer 2
    k_expand2<<<(LSEQ * HID) / 256, 256>>>(out + HID, A2);
    k_gemm<2><<<dim3(HID / 128, LSEQ / 128), 256>>>(A2, W2, nullptr, a2, LSEQ, HID, KF2);

    // y = a2^T p (deterministic two-stage reduction)
    k_ypart<<<32, 512>>>(p);
    k_yfinal<<<2, 256>>>(out);
}